// round 2
// baseline (speedup 1.0000x reference)
#include <cuda_runtime.h>
#include <cstdint>

#define NN 50000
#define EE 800000
#define IND 128
#define HC 256      // HEADS*OUT_DIM
#define CC 64
#define HH 4
#define NEG_SLOPE 0.2f

// ---------------- device scratch (allocation-free rule: __device__ globals) ----
__device__ float g_h[3ull * NN * HC];       // projected features per metapath
__device__ float g_asrc[3ull * NN * HH];
__device__ float g_adst[3ull * NN * HH];
__device__ float g_w[3ull * EE * HH];       // exp(leakyrelu(e)) per edge
__device__ float g_wl[3ull * NN * HH];      // self-loop numerators
__device__ float g_denom[3ull * NN * HH];
__device__ float g_acc[3ull * NN * CC];     // head-summed weighted aggregation

__device__ __forceinline__ float lrelu(float v) {
    return v > 0.f ? v : NEG_SLOPE * v;
}

__device__ __forceinline__ void red_add_v4(float* addr, float4 v) {
    asm volatile("red.global.add.v4.f32 [%0], {%1,%2,%3,%4};"
                 :: "l"(addr), "f"(v.x), "f"(v.y), "f"(v.z), "f"(v.w)
                 : "memory");
}

// ---------------- zero scratch ------------------------------------------------
__global__ void zero_kernel() {
    const size_t nd = 3ull * NN * HH;
    const size_t na = 3ull * NN * CC;
    size_t stride = (size_t)gridDim.x * blockDim.x;
    for (size_t i = blockIdx.x * (size_t)blockDim.x + threadIdx.x; i < nd; i += stride)
        g_denom[i] = 0.f;
    for (size_t i = blockIdx.x * (size_t)blockDim.x + threadIdx.x; i < na; i += stride)
        g_acc[i] = 0.f;
}

// ---------------- GEMM: h = x @ W  (BM=128, BN=64, BK=16, 256 thr, 8x4) -------
__global__ void gemm_kernel(const float* __restrict__ X, const float* __restrict__ W, int mp) {
    __shared__ float As[16][132];
    __shared__ float Bs[16][64];
    float* Hout = &g_h[(size_t)mp * NN * HC];

    int m0 = blockIdx.x * 128;
    int n0 = blockIdx.y * 64;
    int tid = threadIdx.x;
    int tx = tid % 16, ty = tid / 16;

    float acc[8][4];
#pragma unroll
    for (int i = 0; i < 8; i++)
#pragma unroll
        for (int j = 0; j < 4; j++) acc[i][j] = 0.f;

    for (int k0 = 0; k0 < IND; k0 += 16) {
#pragma unroll
        for (int it = 0; it < 2; it++) {
            int m = tid / 4 + it * 64;
            int k = (tid % 4) * 4;
            float4 v = make_float4(0.f, 0.f, 0.f, 0.f);
            int gm = m0 + m;
            if (gm < NN) v = *(const float4*)&X[(size_t)gm * IND + k0 + k];
            As[k + 0][m] = v.x; As[k + 1][m] = v.y;
            As[k + 2][m] = v.z; As[k + 3][m] = v.w;
        }
        {
            int k = tid / 16;
            int n = (tid % 16) * 4;
            float4 v = *(const float4*)&W[(size_t)(k0 + k) * HC + n0 + n];
            *(float4*)&Bs[k][n] = v;
        }
        __syncthreads();
#pragma unroll
        for (int k = 0; k < 16; k++) {
            float a[8], b[4];
            *(float4*)&a[0] = *(float4*)&As[k][ty * 8];
            *(float4*)&a[4] = *(float4*)&As[k][ty * 8 + 4];
            *(float4*)&b[0] = *(float4*)&Bs[k][tx * 4];
#pragma unroll
            for (int i = 0; i < 8; i++)
#pragma unroll
                for (int j = 0; j < 4; j++) acc[i][j] += a[i] * b[j];
        }
        __syncthreads();
    }
#pragma unroll
    for (int i = 0; i < 8; i++) {
        int gm = m0 + ty * 8 + i;
        if (gm < NN)
            *(float4*)&Hout[(size_t)gm * HC + n0 + tx * 4] = *(float4*)&acc[i][0];
    }
}

// ---------------- per-node attention dots -------------------------------------
__global__ void attn_dot_kernel(int mp, const float* __restrict__ att_src,
                                const float* __restrict__ att_dst) {
    int warp = (blockIdx.x * blockDim.x + threadIdx.x) >> 5;
    int lane = threadIdx.x & 31;
    if (warp >= NN * HH) return;
    int n = warp >> 2, h = warp & 3;
    const float* hp = &g_h[(size_t)mp * NN * HC + (size_t)n * HC + h * CC];
    const float* s = &att_src[h * CC];
    const float* d = &att_dst[h * CC];
    float h0 = hp[lane], h1 = hp[lane + 32];
    float vs = h0 * s[lane] + h1 * s[lane + 32];
    float vd = h0 * d[lane] + h1 * d[lane + 32];
#pragma unroll
    for (int o = 16; o > 0; o >>= 1) {
        vs += __shfl_down_sync(0xffffffffu, vs, o);
        vd += __shfl_down_sync(0xffffffffu, vd, o);
    }
    if (lane == 0) {
        g_asrc[(size_t)mp * NN * HH + n * HH + h] = vs;
        g_adst[(size_t)mp * NN * HH + n * HH + h] = vd;
    }
}

// ---------------- edge pass 1: numerators + denom -----------------------------
__global__ void edge_softmax_kernel(const int* __restrict__ ei, int mp) {
    int e = blockIdx.x * blockDim.x + threadIdx.x;
    if (e >= EE) return;
    int s = ei[e], d = ei[EE + e];
    const float* asrc = &g_asrc[(size_t)mp * NN * HH];
    const float* adst = &g_adst[(size_t)mp * NN * HH];
    float4 as = *(const float4*)&asrc[s * HH];
    float4 ad = *(const float4*)&adst[d * HH];
    float4 v;
    v.x = __expf(lrelu(as.x + ad.x));
    v.y = __expf(lrelu(as.y + ad.y));
    v.z = __expf(lrelu(as.z + ad.z));
    v.w = __expf(lrelu(as.w + ad.w));
    *(float4*)&g_w[(size_t)mp * EE * HH + (size_t)e * HH] = v;
    red_add_v4(&g_denom[(size_t)mp * NN * HH + d * HH], v);
}

__global__ void selfloop_kernel(int mp) {
    int n = blockIdx.x * blockDim.x + threadIdx.x;
    if (n >= NN) return;
    const float* asrc = &g_asrc[(size_t)mp * NN * HH];
    const float* adst = &g_adst[(size_t)mp * NN * HH];
    float4 as = *(const float4*)&asrc[n * HH];
    float4 ad = *(const float4*)&adst[n * HH];
    float4 v;
    v.x = __expf(lrelu(as.x + ad.x));
    v.y = __expf(lrelu(as.y + ad.y));
    v.z = __expf(lrelu(as.z + ad.z));
    v.w = __expf(lrelu(as.w + ad.w));
    *(float4*)&g_wl[(size_t)mp * NN * HH + n * HH] = v;
    red_add_v4(&g_denom[(size_t)mp * NN * HH + n * HH], v);
}

// ---------------- edge pass 2: weighted aggregation (16 thr / edge) -----------
__global__ void edge_agg_kernel(const int* __restrict__ ei, int mp) {
    int t = blockIdx.x * blockDim.x + threadIdx.x;
    int e = t >> 4;
    int cg = (t & 15) * 4;
    if (e >= EE) return;
    int s = ei[e], d = ei[EE + e];
    float4 we = *(const float4*)&g_w[(size_t)mp * EE * HH + (size_t)e * HH];
    float4 de = *(const float4*)&g_denom[(size_t)mp * NN * HH + d * HH];
    float a0 = we.x / de.x, a1 = we.y / de.y, a2 = we.z / de.z, a3 = we.w / de.w;
    const float* hp = &g_h[(size_t)mp * NN * HC + (size_t)s * HC];
    float4 h0 = *(const float4*)&hp[cg];
    float4 h1 = *(const float4*)&hp[CC + cg];
    float4 h2 = *(const float4*)&hp[2 * CC + cg];
    float4 h3 = *(const float4*)&hp[3 * CC + cg];
    float4 v;
    v.x = a0 * h0.x + a1 * h1.x + a2 * h2.x + a3 * h3.x;
    v.y = a0 * h0.y + a1 * h1.y + a2 * h2.y + a3 * h3.y;
    v.z = a0 * h0.z + a1 * h1.z + a2 * h2.z + a3 * h3.z;
    v.w = a0 * h0.w + a1 * h1.w + a2 * h2.w + a3 * h3.w;
    red_add_v4(&g_acc[(size_t)mp * NN * CC + (size_t)d * CC + cg], v);
}

// ---------------- finalize: elu + semantic attention --------------------------
__global__ void finalize_kernel(const float* __restrict__ proj_W,
                                const float* __restrict__ proj_b,
                                const float* __restrict__ attn_vec,
                                const float* __restrict__ bias0,
                                const float* __restrict__ bias1,
                                const float* __restrict__ bias2,
                                float* __restrict__ out, int write_beta) {
    __shared__ float Wsm[64 * 64];
    __shared__ float zs[4][3][64];
    __shared__ float sred[4][3];
    __shared__ float bsm[64], av[64], biasm[3][64];
    int tid = threadIdx.x;
    for (int i = tid; i < 64 * 64; i += 256) Wsm[i] = proj_W[i];
    if (tid < 64) {
        bsm[tid] = proj_b[tid];
        av[tid] = attn_vec[tid];
        biasm[0][tid] = bias0[tid];
        biasm[1][tid] = bias1[tid];
        biasm[2][tid] = bias2[tid];
    }
    __syncthreads();

    int g = tid >> 6, j = tid & 63;
    for (int n0 = blockIdx.x * 4; n0 < NN; n0 += gridDim.x * 4) {
        int n = n0 + g;
        bool valid = n < NN;
        float zreg[3] = {0.f, 0.f, 0.f};
        if (valid) {
#pragma unroll
            for (int m = 0; m < 3; m++) {
                float accv = g_acc[(size_t)m * NN * CC + (size_t)n * CC + j];
                float selfv = 0.f;
#pragma unroll
                for (int h = 0; h < HH; h++) {
                    float alpha = g_wl[(size_t)m * NN * HH + n * HH + h] /
                                  g_denom[(size_t)m * NN * HH + n * HH + h];
                    selfv += alpha * g_h[(size_t)m * NN * HC + (size_t)n * HC + h * CC + j];
                }
                float z = (accv + selfv) * 0.25f + biasm[m][j];
                z = z > 0.f ? z : (__expf(z) - 1.0f);
                zreg[m] = z;
                zs[g][m][j] = z;
            }
        } else {
            zs[g][0][j] = 0.f; zs[g][1][j] = 0.f; zs[g][2][j] = 0.f;
        }
        if (j < 3) sred[g][j] = 0.f;
        __syncthreads();

#pragma unroll
        for (int m = 0; m < 3; m++) {
            float t = bsm[j];
#pragma unroll
            for (int c = 0; c < 64; c++) t += zs[g][m][c] * Wsm[c * 64 + j];
            t = tanhf(t);
            float p = t * av[j];
#pragma unroll
            for (int o = 16; o > 0; o >>= 1) p += __shfl_down_sync(0xffffffffu, p, o);
            if ((tid & 31) == 0) atomicAdd(&sred[g][m], p);
        }
        __syncthreads();

        float s0 = sred[g][0], s1 = sred[g][1], s2 = sred[g][2];
        float mx = fmaxf(s0, fmaxf(s1, s2));
        float e0 = __expf(s0 - mx), e1 = __expf(s1 - mx), e2 = __expf(s2 - mx);
        float inv = 1.0f / (e0 + e1 + e2);
        float b0 = e0 * inv, b1 = e1 * inv, b2 = e2 * inv;
        if (valid) {
            out[(size_t)n * CC + j] = b0 * zreg[0] + b1 * zreg[1] + b2 * zreg[2];
            if (write_beta && j < 3)
                out[(size_t)NN * CC + (size_t)n * 3 + j] = (j == 0 ? b0 : (j == 1 ? b1 : b2));
        }
        __syncthreads();
    }
}

// ---------------- launch ------------------------------------------------------
// Input order follows setup_inputs() dict insertion order (metadata.txt):
//   0: x
//   1+5i+0: edge_index_i  (2*E int32)
//   1+5i+1: W_i           (128*256 f32)
//   1+5i+2: att_src_i     (4*64 f32)
//   1+5i+3: att_dst_i     (4*64 f32)
//   1+5i+4: bias_i        (64 f32)
//   16: proj_W, 17: proj_b, 18: attn_vec
extern "C" void kernel_launch(void* const* d_in, const int* in_sizes, int n_in,
                              void* d_out, int out_size) {
    const float* x = (const float*)d_in[0];
    const int* ei[3];
    const float *W[3], *att_src[3], *att_dst[3], *bias[3];
    for (int i = 0; i < 3; i++) {
        ei[i]      = (const int*)d_in[1 + 5 * i + 0];
        W[i]       = (const float*)d_in[1 + 5 * i + 1];
        att_src[i] = (const float*)d_in[1 + 5 * i + 2];
        att_dst[i] = (const float*)d_in[1 + 5 * i + 3];
        bias[i]    = (const float*)d_in[1 + 5 * i + 4];
    }
    const float* projW = (const float*)d_in[16];
    const float* projb = (const float*)d_in[17];
    const float* attnv = (const float*)d_in[18];
    float* out = (float*)d_out;

    // Defensive sanity: if the layout is not what we expect, do nothing harmful.
    // (edge_index must be 2*E ints; x must be N*IND floats.)
    if (in_sizes[0] != NN * IND || in_sizes[1] != 2 * EE) {
        // Fallback: try grouped layout (x, ei0..2, W0..2, as0..2, ad0..2, b0..2, ...)
        for (int i = 0; i < 3; i++) {
            ei[i]      = (const int*)d_in[1 + i];
            W[i]       = (const float*)d_in[4 + i];
            att_src[i] = (const float*)d_in[7 + i];
            att_dst[i] = (const float*)d_in[10 + i];
            bias[i]    = (const float*)d_in[13 + i];
        }
    }

    zero_kernel<<<2048, 256>>>();

    dim3 gg((NN + 127) / 128, HC / 64);
    for (int i = 0; i < 3; i++) {
        gemm_kernel<<<gg, 256>>>(x, W[i], i);
        attn_dot_kernel<<<(NN * HH * 32) / 256, 256>>>(i, att_src[i], att_dst[i]);
    }
    for (int i = 0; i < 3; i++) {
        edge_softmax_kernel<<<EE / 256, 256>>>(ei[i], i);
        selfloop_kernel<<<(NN + 255) / 256, 256>>>(i);
    }
    for (int i = 0; i < 3; i++) {
        edge_agg_kernel<<<(EE * 16) / 256, 256>>>(ei[i], i);
    }
    int wb = (out_size >= NN * CC + NN * 3) ? 1 : 0;
    finalize_kernel<<<512, 256>>>(projW, projb, attnv, bias[0], bias[1], bias[2], out, wb);
}